// round 13
// baseline (speedup 1.0000x reference)
#include <cuda_runtime.h>
#include <cuda_fp16.h>
#include <cstdint>
#include <math_constants.h>

// ---------------------------------------------------------------------------
// RWKV TimeMix: T=4096, C=2048
//   fp16 mma.sync GEMMs (128x128 tile, warp 64x64, occ 2, pitch-20 smem,
//   cp.async 4-stage, ldmatrix fragment loads) + chunk-parallel WKV scan
//   (128 chunks, 4ch/thread, warp-scan carry) + fused transpose/mix prep.
//   r projection stored fp16 (only consumed through sigmoid).
// ---------------------------------------------------------------------------

#define TT 4096
#define CC 2048
#define NCHUNK 128
#define CHUNK (TT / NCHUNK)   // 32

// Scratch (device globals: no allocation allowed anywhere)
__device__ __half g_xk[TT * CC];
__device__ __half g_xv[TT * CC];
__device__ __half g_xr[TT * CC];
__device__ __half g_y [TT * CC];          // gated output (Wo GEMM A operand)
__device__ __half g_r [TT * CC];          // r projection (fp16: sigmoid input)
__device__ float  g_k [TT * CC];
__device__ float  g_v [TT * CC];
// chunk states, channel-major: [c * NCHUNK + ch]
__device__ float  g_lp[CC * NCHUNK];
__device__ float  g_lq[CC * NCHUNK];
__device__ float  g_lo[CC * NCHUNK];
__device__ float  g_cp[CC * NCHUNK];
__device__ float  g_cq[CC * NCHUNK];
__device__ float  g_co[CC * NCHUNK];
// K-major (transposed) weights, fp16
__device__ __half g_WkT[CC * CC];
__device__ __half g_WvT[CC * CC];
__device__ __half g_WrT[CC * CC];
__device__ __half g_WoT[CC * CC];

// ---------------------------------------------------------------------------
// Helpers
// ---------------------------------------------------------------------------
__device__ __forceinline__ uint32_t smem_u32(const void* p) {
    uint32_t a;
    asm("{ .reg .u64 t; cvta.to.shared.u64 t, %1; cvt.u32.u64 %0, t; }"
        : "=r"(a) : "l"(p));
    return a;
}

__device__ __forceinline__ unsigned h2u(__half2 h) {
    return *reinterpret_cast<unsigned*>(&h);
}

// epilogue store helpers (overloaded on output type)
__device__ __forceinline__ void epi_store2(float* D, size_t off, float a, float b) {
    *(float2*)&D[off] = make_float2(a, b);
}
__device__ __forceinline__ void epi_store2(__half* D, size_t off, float a, float b) {
    *(__half2*)&D[off] = __floats2half2_rn(a, b);
}

// ---------------------------------------------------------------------------
// Fused prep: blocks [0, 16384) transpose the 4 weights -> fp16 K-major;
//             blocks [16384, 24576) do the time-mix -> fp16 operands.
// ---------------------------------------------------------------------------
#define TRANS_BLOCKS (4 * (CC / 32) * (CC / 32))   // 16384
#define MIX_BLOCKS   ((TT * CC / 4) / 256)         // 8192

__global__ __launch_bounds__(256) void prep_kernel(
    const float* __restrict__ x,
    const float* __restrict__ tmk,
    const float* __restrict__ tmv,
    const float* __restrict__ tmr,
    const float* __restrict__ W0, const float* __restrict__ W1,
    const float* __restrict__ W2, const float* __restrict__ W3)
{
    const int bid = blockIdx.x;
    const int tid = threadIdx.x;

    if (bid < TRANS_BLOCKS) {
        __shared__ float t[32][33];
        int z = bid >> 12;               // 4096 blocks per matrix
        int r = bid & 4095;
        int bx = (r & 63) * 32;
        int by = (r >> 6) * 32;
        const float* W;
        __half* WT;
        switch (z) {
            case 0:  W = W0; WT = g_WkT; break;
            case 1:  W = W1; WT = g_WvT; break;
            case 2:  W = W2; WT = g_WrT; break;
            default: W = W3; WT = g_WoT; break;
        }
        int tx = tid & 31, ty = tid >> 5;          // 32 x 8
#pragma unroll
        for (int j = 0; j < 32; j += 8)
            t[ty + j][tx] = W[(size_t)(by + ty + j) * CC + bx + tx];
        __syncthreads();
#pragma unroll
        for (int j = 0; j < 32; j += 8)
            WT[(size_t)(bx + ty + j) * CC + by + tx] = __float2half(t[tx][ty + j]);
        return;
    }

    // ---- mix ----
    int i4 = (bid - TRANS_BLOCKS) * 256 + tid;    // float4 index over T*C/4
    int c4 = i4 & (CC / 4 - 1);

    float4 xc = ((const float4*)x)[i4];
    float4 xp;
    if (i4 >= CC / 4) xp = ((const float4*)x)[i4 - CC / 4];
    else              xp = make_float4(0.f, 0.f, 0.f, 0.f);

    float4 mk = ((const float4*)tmk)[c4];
    float4 mv = ((const float4*)tmv)[c4];
    float4 mr = ((const float4*)tmr)[c4];

    __half2 k01 = __floats2half2_rn(xp.x + mk.x * (xc.x - xp.x), xp.y + mk.y * (xc.y - xp.y));
    __half2 k23 = __floats2half2_rn(xp.z + mk.z * (xc.z - xp.z), xp.w + mk.w * (xc.w - xp.w));
    __half2 v01 = __floats2half2_rn(xp.x + mv.x * (xc.x - xp.x), xp.y + mv.y * (xc.y - xp.y));
    __half2 v23 = __floats2half2_rn(xp.z + mv.z * (xc.z - xp.z), xp.w + mv.w * (xc.w - xp.w));
    __half2 r01 = __floats2half2_rn(xp.x + mr.x * (xc.x - xp.x), xp.y + mr.y * (xc.y - xp.y));
    __half2 r23 = __floats2half2_rn(xp.z + mr.z * (xc.z - xp.z), xp.w + mr.w * (xc.w - xp.w));

    ((uint2*)g_xk)[i4] = make_uint2(h2u(k01), h2u(k23));
    ((uint2*)g_xv)[i4] = make_uint2(h2u(v01), h2u(v23));
    ((uint2*)g_xr)[i4] = make_uint2(h2u(r01), h2u(r23));
}

// ---------------------------------------------------------------------------
// FP16 GEMM: D[M,N] = A[M,K] @ Bt[N,K]^T  (both k-contiguous, half)
// Block 128x128, BK=32, 128 threads (4 warps, warp tile 64x64),
// 4-stage cp.async pipeline, pitch-20-word smem, ldmatrix fragment loads.
// Output type templated: fp32 (k, v, out) or fp16 (r).
// ---------------------------------------------------------------------------
#define BM 128
#define BN 128
#define BK 32
#define PITCHW 20                    // 32-bit words per row (32 halves + 8 pad)
#define PITCHB (PITCHW * 4)          // 80 bytes per row
#define AST_W (BM * PITCHW)          // 2560 words per A tile
#define STAGE_B (2 * AST_W * 4)      // 20480 bytes (A + B)
#define NSTAGE 4
#define SMEM_BYTES (NSTAGE * STAGE_B)   // 81920
#define NKT (CC / BK)                // 64

__device__ __forceinline__ void mma_f16(float* d, const unsigned* a, const unsigned* b) {
    asm volatile(
        "mma.sync.aligned.m16n8k16.row.col.f32.f16.f16.f32 "
        "{%0,%1,%2,%3}, {%4,%5,%6,%7}, {%8,%9}, {%0,%1,%2,%3};\n"
        : "+f"(d[0]), "+f"(d[1]), "+f"(d[2]), "+f"(d[3])
        : "r"(a[0]), "r"(a[1]), "r"(a[2]), "r"(a[3]), "r"(b[0]), "r"(b[1]));
}

__device__ __forceinline__ void cp16(uint32_t saddr, const void* gaddr) {
    asm volatile("cp.async.cg.shared.global [%0], [%1], 16;\n"
                 :: "r"(saddr), "l"(gaddr));
}

__device__ __forceinline__ void ldsm4(unsigned& r0, unsigned& r1,
                                      unsigned& r2, unsigned& r3, uint32_t addr) {
    asm volatile(
        "ldmatrix.sync.aligned.m8n8.x4.shared.b16 {%0,%1,%2,%3}, [%4];"
        : "=r"(r0), "=r"(r1), "=r"(r2), "=r"(r3) : "r"(addr));
}

template <typename OT>
__device__ __forceinline__ void gemm_body(
    const __half* __restrict__ A, const __half* __restrict__ Bt,
    OT* __restrict__ D, char* smem)
{
    const uint32_t sbase = smem_u32(smem);
    const int tid = threadIdx.x;
    const int wid = tid >> 5;
    const int lane = tid & 31;
    const int gp = lane >> 2;        // 0..7
    const int tg = lane & 3;         // 0..3
    const int wm = (wid & 1) << 6;   // 0, 64
    const int wn = (wid >> 1) << 6;  // 0, 64

    const int bm = blockIdx.y * BM;
    const int bn = blockIdx.x * BN;

    const int lr = tid >> 2;         // 0..31
    const int lc = tid & 3;          // 0..3
    const __half* ga = A  + (size_t)(bm + lr) * CC + lc * 8;
    const __half* gb = Bt + (size_t)(bn + lr) * CC + lc * 8;
    const uint32_t swa = (uint32_t)(lr * PITCHB + lc * 16);

    // ldmatrix per-lane byte offsets (within stage)
    uint32_t aoff[4];
#pragma unroll
    for (int mi = 0; mi < 4; mi++)
        aoff[mi] = (uint32_t)((wm + mi * 16 + (lane & 15)) * PITCHB + (lane >> 4) * 16);
    uint32_t boff[4];
#pragma unroll
    for (int p = 0; p < 4; p++)
        boff[p] = (uint32_t)(AST_W * 4 +
                  (wn + p * 16 + (lane & 7) + ((lane >> 4) << 3)) * PITCHB +
                  ((lane >> 3) & 1) * 16);

    float acc[4][8][4];
#pragma unroll
    for (int i = 0; i < 4; i++)
#pragma unroll
        for (int j = 0; j < 8; j++)
#pragma unroll
            for (int e = 0; e < 4; e++) acc[i][j][e] = 0.f;

#define LOAD_STAGE(ST, KT)                                                     \
    do {                                                                       \
        uint32_t _sa = sbase + (ST) * STAGE_B + swa;                           \
        uint32_t _sb = _sa + AST_W * 4;                                        \
        const __half* _ga = ga + (KT) * BK;                                    \
        const __half* _gb = gb + (KT) * BK;                                    \
        cp16(_sa,                  _ga);                                       \
        cp16(_sa + 32 * PITCHB,    _ga + (size_t)32 * CC);                     \
        cp16(_sa + 64 * PITCHB,    _ga + (size_t)64 * CC);                     \
        cp16(_sa + 96 * PITCHB,    _ga + (size_t)96 * CC);                     \
        cp16(_sb,                  _gb);                                       \
        cp16(_sb + 32 * PITCHB,    _gb + (size_t)32 * CC);                     \
        cp16(_sb + 64 * PITCHB,    _gb + (size_t)64 * CC);                     \
        cp16(_sb + 96 * PITCHB,    _gb + (size_t)96 * CC);                     \
        asm volatile("cp.async.commit_group;\n" ::: "memory");                 \
    } while (0)

    LOAD_STAGE(0, 0);
    LOAD_STAGE(1, 1);
    LOAD_STAGE(2, 2);

    for (int kt = 0; kt < NKT; kt++) {
        int ahead = NKT - 1 - kt;
        if (ahead >= 2)      asm volatile("cp.async.wait_group 2;\n" ::: "memory");
        else if (ahead == 1) asm volatile("cp.async.wait_group 1;\n" ::: "memory");
        else                 asm volatile("cp.async.wait_group 0;\n" ::: "memory");
        __syncthreads();

        if (kt + 3 < NKT) LOAD_STAGE((kt + 3) & 3, kt + 3);

        const uint32_t sA = sbase + (kt & 3) * STAGE_B;

#pragma unroll
        for (int ks = 0; ks < 2; ks++) {       // two k16 steps (+32 bytes each)
            const uint32_t ko = ks * 32;
            unsigned af[4][4];
            unsigned bf[8][2];
#pragma unroll
            for (int mi = 0; mi < 4; mi++)
                ldsm4(af[mi][0], af[mi][1], af[mi][2], af[mi][3],
                      sA + aoff[mi] + ko);
#pragma unroll
            for (int p = 0; p < 4; p++)
                ldsm4(bf[2 * p][0], bf[2 * p][1], bf[2 * p + 1][0], bf[2 * p + 1][1],
                      sA + boff[p] + ko);
#pragma unroll
            for (int mi = 0; mi < 4; mi++)
#pragma unroll
                for (int ni = 0; ni < 8; ni++)
                    mma_f16(acc[mi][ni], af[mi], bf[ni]);
        }
    }

    // epilogue
#pragma unroll
    for (int mi = 0; mi < 4; mi++) {
        int r0 = bm + wm + mi * 16 + gp;
#pragma unroll
        for (int ni = 0; ni < 8; ni++) {
            int c0 = bn + wn + ni * 8 + tg * 2;
            epi_store2(D, (size_t)r0 * CC + c0,       acc[mi][ni][0], acc[mi][ni][1]);
            epi_store2(D, (size_t)(r0 + 8) * CC + c0, acc[mi][ni][2], acc[mi][ni][3]);
        }
    }
#undef LOAD_STAGE
}

// Fused k/v/r GEMMs: blockIdx.z selects operand triple (wave packing)
__global__ __launch_bounds__(128, 2) void gemm_fused3()
{
    extern __shared__ char smem[];
    if (blockIdx.z == 0)      gemm_body<float>(g_xk, g_WkT, g_k, smem);
    else if (blockIdx.z == 1) gemm_body<float>(g_xv, g_WvT, g_v, smem);
    else                      gemm_body<__half>(g_xr, g_WrT, g_r, smem);
}

__global__ __launch_bounds__(128, 2) void gemm_single(
    const __half* __restrict__ A, const __half* __restrict__ Bt, float* __restrict__ D)
{
    extern __shared__ char smem[];
    gemm_body<float>(A, Bt, D, smem);
}

// ---------------------------------------------------------------------------
// WKV chunk-parallel scan; A/C process 4 channels/thread (float4 loads);
// chunk-state arrays are channel-major [c*NCHUNK+ch] for phaseB coalescing.
// ---------------------------------------------------------------------------
__global__ __launch_bounds__(128) void wkv_phaseA(const float* __restrict__ time_decay)
{
    int t = blockIdx.x * 128 + threadIdx.x;       // 0..511
    int c = t * 4;
    int ch = blockIdx.y;
    float4 td4 = *(const float4*)&time_decay[c];
    float w[4] = {-__expf(td4.x), -__expf(td4.y), -__expf(td4.z), -__expf(td4.w)};
    float p[4] = {0.f, 0.f, 0.f, 0.f};
    float q[4] = {0.f, 0.f, 0.f, 0.f};
    float o[4] = {-CUDART_INF_F, -CUDART_INF_F, -CUDART_INF_F, -CUDART_INF_F};
    size_t idx = (size_t)(ch * CHUNK) * CC + c;
#pragma unroll 2
    for (int i = 0; i < CHUNK; i++, idx += CC) {
        float4 kt4 = *(const float4*)&g_k[idx];
        float4 vt4 = *(const float4*)&g_v[idx];
        float kt[4] = {kt4.x, kt4.y, kt4.z, kt4.w};
        float vt[4] = {vt4.x, vt4.y, vt4.z, vt4.w};
#pragma unroll
        for (int j = 0; j < 4; j++) {
            float no = fmaxf(w[j] + o[j], kt[j]);
            float A2 = __expf(w[j] + o[j] - no);
            float B2 = __expf(kt[j] - no);
            p[j] = A2 * p[j] + B2 * vt[j];
            q[j] = A2 * q[j] + B2;
            o[j] = no;
        }
    }
#pragma unroll
    for (int j = 0; j < 4; j++) {
        g_lp[(c + j) * NCHUNK + ch] = p[j];
        g_lq[(c + j) * NCHUNK + ch] = q[j];
        g_lo[(c + j) * NCHUNK + ch] = o[j];
    }
}

// Warp-scan carry combine: one warp per channel, lane l holds chunks 4l..4l+3.
__global__ __launch_bounds__(256) void wkv_phaseB(const float* __restrict__ time_decay)
{
    const int lane = threadIdx.x & 31;
    const int c = blockIdx.x * 8 + (threadIdx.x >> 5);   // grid 256
    const float w = -__expf(time_decay[c]);
    const float d = w * (float)CHUNK;

    const int base = c * NCHUNK + lane * 4;
    const float4 lp4 = *(const float4*)&g_lp[base];
    const float4 lq4 = *(const float4*)&g_lq[base];
    const float4 lo4 = *(const float4*)&g_lo[base];
    const float lp[4] = {lp4.x, lp4.y, lp4.z, lp4.w};
    const float lq[4] = {lq4.x, lq4.y, lq4.z, lq4.w};
    const float lo[4] = {lo4.x, lo4.y, lo4.z, lo4.w};

    float ep[4], eq[4], eo[4];
    float p = 0.f, q = 0.f, o = -CUDART_INF_F;
#pragma unroll
    for (int m = 0; m < 4; m++) {
        ep[m] = p; eq[m] = q; eo[m] = o;
        float o1 = o + d;
        float no = fmaxf(o1, lo[m]);
        float A = __expf(o1 - no);
        float B = __expf(lo[m] - no);
        p = A * p + B * lp[m];
        q = A * q + B * lq[m];
        o = no;
    }

#pragma unroll
    for (int k = 1; k <= 16; k <<= 1) {
        float pp = __shfl_up_sync(0xffffffffu, p, k);
        float qq = __shfl_up_sync(0xffffffffu, q, k);
        float oo = __shfl_up_sync(0xffffffffu, o, k);
        if (lane >= k) {
            float o1 = oo + d * (float)(4 * k);
            float no = fmaxf(o1, o);
            float A = __expf(o1 - no);
            float B = __expf(o - no);
            p = A * pp + B * p;
            q = A * qq + B * q;
            o = no;
        }
    }

    float Pp = __shfl_up_sync(0xffffffffu, p, 1);
    float Pq = __shfl_up_sync(0xffffffffu, q, 1);
    float Po = __shfl_up_sync(0xffffffffu, o, 1);
    if (lane == 0) { Pp = 0.f; Pq = 0.f; Po = -CUDART_INF_F; }

    float cp[4], cq[4], co[4];
    cp[0] = Pp; cq[0] = Pq; co[0] = Po;
#pragma unroll
    for (int m = 1; m < 4; m++) {
        float o1 = Po + d * (float)m;
        float no = fmaxf(o1, eo[m]);
        float A = __expf(o1 - no);
        float B = __expf(eo[m] - no);
        cp[m] = A * Pp + B * ep[m];
        cq[m] = A * Pq + B * eq[m];
        co[m] = no;
    }
    *(float4*)&g_cp[base] = make_float4(cp[0], cp[1], cp[2], cp[3]);
    *(float4*)&g_cq[base] = make_float4(cq[0], cq[1], cq[2], cq[3]);
    *(float4*)&g_co[base] = make_float4(co[0], co[1], co[2], co[3]);
}

// fuses sigmoid(r) gate; fp16 output (Wo GEMM A operand); 4 channels/thread
__global__ __launch_bounds__(128) void wkv_phaseC(
    const float* __restrict__ time_decay, const float* __restrict__ time_first)
{
    int t = blockIdx.x * 128 + threadIdx.x;       // 0..511
    int c = t * 4;
    int ch = blockIdx.y;
    float4 td4 = *(const float4*)&time_decay[c];
    float4 tf4 = *(const float4*)&time_first[c];
    float w[4] = {-__expf(td4.x), -__expf(td4.y), -__expf(td4.z), -__expf(td4.w)};
    float u[4] = {tf4.x, tf4.y, tf4.z, tf4.w};
    float p[4], q[4], o[4];
#pragma unroll
    for (int j = 0; j < 4; j++) {
        p[j] = g_cp[(c + j) * NCHUNK + ch];
        q[j] = g_cq[(c + j) * NCHUNK + ch];
        o[j] = g_co[(c + j) * NCHUNK + ch];
    }
    size_t idx = (size_t)(ch * CHUNK) * CC + c;
#pragma unroll 2
    for (int i = 0; i < CHUNK; i++, idx += CC) {
        float4 kt4 = *(const float4*)&g_k[idx];
        float4 vt4 = *(const float4*)&g_v[idx];
        uint2 rraw = *(const uint2*)&g_r[idx];
        __half2 r01 = *reinterpret_cast<__half2*>(&rraw.x);
        __half2 r23 = *reinterpret_cast<__half2*>(&rraw.y);
        float2 rf01 = __half22float2(r01);
        float2 rf23 = __half22float2(r23);
        float kt[4] = {kt4.x, kt4.y, kt4.z, kt4.w};
        float vt[4] = {vt4.x, vt4.y, vt4.z, vt4.w};
        float rt[4] = {rf01.x, rf01.y, rf23.x, rf23.y};
        float yv[4];
#pragma unroll
        for (int j = 0; j < 4; j++) {
            float uk = u[j] + kt[j];
            float no = fmaxf(o[j], uk);
            float Ae = __expf(o[j] - no);
            float Be = __expf(uk - no);
            float y = __fdividef(Ae * p[j] + Be * vt[j], Ae * q[j] + Be);
            float sr = __fdividef(1.f, 1.f + __expf(-rt[j]));
            yv[j] = sr * y;
            float no2 = fmaxf(w[j] + o[j], kt[j]);
            float A2 = __expf(w[j] + o[j] - no2);
            float B2 = __expf(kt[j] - no2);
            p[j] = A2 * p[j] + B2 * vt[j];
            q[j] = A2 * q[j] + B2;
            o[j] = no2;
        }
        __half2 y01 = __floats2half2_rn(yv[0], yv[1]);
        __half2 y23 = __floats2half2_rn(yv[2], yv[3]);
        *(uint2*)&g_y[idx] = make_uint2(h2u(y01), h2u(y23));
    }
}

// ---------------------------------------------------------------------------
// Launch
// ---------------------------------------------------------------------------
extern "C" void kernel_launch(void* const* d_in, const int* in_sizes, int n_in,
                              void* d_out, int out_size)
{
    (void)in_sizes; (void)n_in; (void)out_size;
    const float* x   = (const float*)d_in[0];
    const float* tfi = (const float*)d_in[1];
    const float* tmk = (const float*)d_in[2];
    const float* tmv = (const float*)d_in[3];
    const float* tmr = (const float*)d_in[4];
    const float* td  = (const float*)d_in[5];
    const float* Wk  = (const float*)d_in[6];
    const float* Wv  = (const float*)d_in[7];
    const float* Wr  = (const float*)d_in[8];
    const float* Wo  = (const float*)d_in[9];
    float* out = (float*)d_out;

    __half *p_y, *p_WoT;
    cudaGetSymbolAddress((void**)&p_y,  g_y);
    cudaGetSymbolAddress((void**)&p_WoT, g_WoT);

    cudaFuncSetAttribute(gemm_fused3, cudaFuncAttributeMaxDynamicSharedMemorySize, SMEM_BYTES);
    cudaFuncSetAttribute(gemm_single, cudaFuncAttributeMaxDynamicSharedMemorySize, SMEM_BYTES);

    prep_kernel<<<TRANS_BLOCKS + MIX_BLOCKS, 256>>>(x, tmk, tmv, tmr, Wk, Wv, Wr, Wo);

    dim3 g3(CC / BN, TT / BM, 3);   // (16, 32, 3) = 1536 CTAs
    gemm_fused3<<<g3, 128, SMEM_BYTES>>>();

    wkv_phaseA<<<dim3(CC / 512, NCHUNK), 128>>>(td);
    wkv_phaseB<<<CC / 8, 256>>>(td);
    wkv_phaseC<<<dim3(CC / 512, NCHUNK), 128>>>(td, tfi);

    dim3 g1(CC / BN, TT / BM);      // (16, 32) = 512 CTAs
    gemm_single<<<g1, 128, SMEM_BYTES>>>(p_y, p_WoT, out);
}

// round 14
// speedup vs baseline: 1.0310x; 1.0310x over previous
#include <cuda_runtime.h>
#include <cuda_fp16.h>
#include <cstdint>
#include <math_constants.h>

// ---------------------------------------------------------------------------
// RWKV TimeMix: T=4096, C=2048
//   fp16 mma.sync GEMMs (128x128 tile, warp 64x64, occ 2, pitch-20 smem,
//   cp.async 4-stage, ldmatrix fragment loads — exact R12 config) +
//   chunk-parallel WKV scan (128 chunks, 4ch/thread, warp-scan carry) +
//   fused transpose/mix prep.
// ---------------------------------------------------------------------------

#define TT 4096
#define CC 2048
#define NCHUNK 128
#define CHUNK (TT / NCHUNK)   // 32

// Scratch (device globals: no allocation allowed anywhere)
__device__ __half g_xk[TT * CC];
__device__ __half g_xv[TT * CC];
__device__ __half g_xr[TT * CC];
__device__ __half g_y [TT * CC];          // gated output (Wo GEMM A operand)
__device__ float  g_k [TT * CC];
__device__ float  g_v [TT * CC];
__device__ float  g_r [TT * CC];
// chunk states, channel-major: [c * NCHUNK + ch]
__device__ float  g_lp[CC * NCHUNK];
__device__ float  g_lq[CC * NCHUNK];
__device__ float  g_lo[CC * NCHUNK];
__device__ float  g_cp[CC * NCHUNK];
__device__ float  g_cq[CC * NCHUNK];
__device__ float  g_co[CC * NCHUNK];
// K-major (transposed) weights, fp16
__device__ __half g_WkT[CC * CC];
__device__ __half g_WvT[CC * CC];
__device__ __half g_WrT[CC * CC];
__device__ __half g_WoT[CC * CC];

// ---------------------------------------------------------------------------
// Helpers
// ---------------------------------------------------------------------------
__device__ __forceinline__ uint32_t smem_u32(const void* p) {
    uint32_t a;
    asm("{ .reg .u64 t; cvta.to.shared.u64 t, %1; cvt.u32.u64 %0, t; }"
        : "=r"(a) : "l"(p));
    return a;
}

__device__ __forceinline__ unsigned h2u(__half2 h) {
    return *reinterpret_cast<unsigned*>(&h);
}

// ---------------------------------------------------------------------------
// Fused prep: blocks [0, 16384) transpose the 4 weights -> fp16 K-major;
//             blocks [16384, 24576) do the time-mix -> fp16 operands.
// ---------------------------------------------------------------------------
#define TRANS_BLOCKS (4 * (CC / 32) * (CC / 32))   // 16384
#define MIX_BLOCKS   ((TT * CC / 4) / 256)         // 8192

__global__ __launch_bounds__(256) void prep_kernel(
    const float* __restrict__ x,
    const float* __restrict__ tmk,
    const float* __restrict__ tmv,
    const float* __restrict__ tmr,
    const float* __restrict__ W0, const float* __restrict__ W1,
    const float* __restrict__ W2, const float* __restrict__ W3)
{
    const int bid = blockIdx.x;
    const int tid = threadIdx.x;

    if (bid < TRANS_BLOCKS) {
        __shared__ float t[32][33];
        int z = bid >> 12;               // 4096 blocks per matrix
        int r = bid & 4095;
        int bx = (r & 63) * 32;
        int by = (r >> 6) * 32;
        const float* W;
        __half* WT;
        switch (z) {
            case 0:  W = W0; WT = g_WkT; break;
            case 1:  W = W1; WT = g_WvT; break;
            case 2:  W = W2; WT = g_WrT; break;
            default: W = W3; WT = g_WoT; break;
        }
        int tx = tid & 31, ty = tid >> 5;          // 32 x 8
#pragma unroll
        for (int j = 0; j < 32; j += 8)
            t[ty + j][tx] = W[(size_t)(by + ty + j) * CC + bx + tx];
        __syncthreads();
#pragma unroll
        for (int j = 0; j < 32; j += 8)
            WT[(size_t)(bx + ty + j) * CC + by + tx] = __float2half(t[tx][ty + j]);
        return;
    }

    // ---- mix ----
    int i4 = (bid - TRANS_BLOCKS) * 256 + tid;    // float4 index over T*C/4
    int c4 = i4 & (CC / 4 - 1);

    float4 xc = ((const float4*)x)[i4];
    float4 xp;
    if (i4 >= CC / 4) xp = ((const float4*)x)[i4 - CC / 4];
    else              xp = make_float4(0.f, 0.f, 0.f, 0.f);

    float4 mk = ((const float4*)tmk)[c4];
    float4 mv = ((const float4*)tmv)[c4];
    float4 mr = ((const float4*)tmr)[c4];

    __half2 k01 = __floats2half2_rn(xp.x + mk.x * (xc.x - xp.x), xp.y + mk.y * (xc.y - xp.y));
    __half2 k23 = __floats2half2_rn(xp.z + mk.z * (xc.z - xp.z), xp.w + mk.w * (xc.w - xp.w));
    __half2 v01 = __floats2half2_rn(xp.x + mv.x * (xc.x - xp.x), xp.y + mv.y * (xc.y - xp.y));
    __half2 v23 = __floats2half2_rn(xp.z + mv.z * (xc.z - xp.z), xp.w + mv.w * (xc.w - xp.w));
    __half2 r01 = __floats2half2_rn(xp.x + mr.x * (xc.x - xp.x), xp.y + mr.y * (xc.y - xp.y));
    __half2 r23 = __floats2half2_rn(xp.z + mr.z * (xc.z - xp.z), xp.w + mr.w * (xc.w - xp.w));

    ((uint2*)g_xk)[i4] = make_uint2(h2u(k01), h2u(k23));
    ((uint2*)g_xv)[i4] = make_uint2(h2u(v01), h2u(v23));
    ((uint2*)g_xr)[i4] = make_uint2(h2u(r01), h2u(r23));
}

// ---------------------------------------------------------------------------
// FP16 GEMM: D[M,N] = A[M,K] @ Bt[N,K]^T  (both k-contiguous, half)
// Block 128x128, BK=32, 128 threads (4 warps, warp tile 64x64),
// 4-stage cp.async pipeline, pitch-20-word smem, ldmatrix fragment loads.
// (Exact R12 configuration — single fp32-output instantiation.)
// ---------------------------------------------------------------------------
#define BM 128
#define BN 128
#define BK 32
#define PITCHW 20                    // 32-bit words per row (32 halves + 8 pad)
#define PITCHB (PITCHW * 4)          // 80 bytes per row
#define AST_W (BM * PITCHW)          // 2560 words per A tile
#define STAGE_B (2 * AST_W * 4)      // 20480 bytes (A + B)
#define NSTAGE 4
#define SMEM_BYTES (NSTAGE * STAGE_B)   // 81920
#define NKT (CC / BK)                // 64

__device__ __forceinline__ void mma_f16(float* d, const unsigned* a, const unsigned* b) {
    asm volatile(
        "mma.sync.aligned.m16n8k16.row.col.f32.f16.f16.f32 "
        "{%0,%1,%2,%3}, {%4,%5,%6,%7}, {%8,%9}, {%0,%1,%2,%3};\n"
        : "+f"(d[0]), "+f"(d[1]), "+f"(d[2]), "+f"(d[3])
        : "r"(a[0]), "r"(a[1]), "r"(a[2]), "r"(a[3]), "r"(b[0]), "r"(b[1]));
}

__device__ __forceinline__ void cp16(uint32_t saddr, const void* gaddr) {
    asm volatile("cp.async.cg.shared.global [%0], [%1], 16;\n"
                 :: "r"(saddr), "l"(gaddr));
}

__device__ __forceinline__ void ldsm4(unsigned& r0, unsigned& r1,
                                      unsigned& r2, unsigned& r3, uint32_t addr) {
    asm volatile(
        "ldmatrix.sync.aligned.m8n8.x4.shared.b16 {%0,%1,%2,%3}, [%4];"
        : "=r"(r0), "=r"(r1), "=r"(r2), "=r"(r3) : "r"(addr));
}

__device__ __forceinline__ void gemm_body(
    const __half* __restrict__ A, const __half* __restrict__ Bt,
    float* __restrict__ D, char* smem)
{
    const uint32_t sbase = smem_u32(smem);
    const int tid = threadIdx.x;
    const int wid = tid >> 5;
    const int lane = tid & 31;
    const int gp = lane >> 2;        // 0..7
    const int tg = lane & 3;         // 0..3
    const int wm = (wid & 1) << 6;   // 0, 64
    const int wn = (wid >> 1) << 6;  // 0, 64

    const int bm = blockIdx.y * BM;
    const int bn = blockIdx.x * BN;

    const int lr = tid >> 2;         // 0..31
    const int lc = tid & 3;          // 0..3
    const __half* ga = A  + (size_t)(bm + lr) * CC + lc * 8;
    const __half* gb = Bt + (size_t)(bn + lr) * CC + lc * 8;
    const uint32_t swa = (uint32_t)(lr * PITCHB + lc * 16);

    // ldmatrix per-lane byte offsets (within stage)
    uint32_t aoff[4];
#pragma unroll
    for (int mi = 0; mi < 4; mi++)
        aoff[mi] = (uint32_t)((wm + mi * 16 + (lane & 15)) * PITCHB + (lane >> 4) * 16);
    uint32_t boff[4];
#pragma unroll
    for (int p = 0; p < 4; p++)
        boff[p] = (uint32_t)(AST_W * 4 +
                  (wn + p * 16 + (lane & 7) + ((lane >> 4) << 3)) * PITCHB +
                  ((lane >> 3) & 1) * 16);

    float acc[4][8][4];
#pragma unroll
    for (int i = 0; i < 4; i++)
#pragma unroll
        for (int j = 0; j < 8; j++)
#pragma unroll
            for (int e = 0; e < 4; e++) acc[i][j][e] = 0.f;

#define LOAD_STAGE(ST, KT)                                                     \
    do {                                                                       \
        uint32_t _sa = sbase + (ST) * STAGE_B + swa;                           \
        uint32_t _sb = _sa + AST_W * 4;                                        \
        const __half* _ga = ga + (KT) * BK;                                    \
        const __half* _gb = gb + (KT) * BK;                                    \
        cp16(_sa,                  _ga);                                       \
        cp16(_sa + 32 * PITCHB,    _ga + (size_t)32 * CC);                     \
        cp16(_sa + 64 * PITCHB,    _ga + (size_t)64 * CC);                     \
        cp16(_sa + 96 * PITCHB,    _ga + (size_t)96 * CC);                     \
        cp16(_sb,                  _gb);                                       \
        cp16(_sb + 32 * PITCHB,    _gb + (size_t)32 * CC);                     \
        cp16(_sb + 64 * PITCHB,    _gb + (size_t)64 * CC);                     \
        cp16(_sb + 96 * PITCHB,    _gb + (size_t)96 * CC);                     \
        asm volatile("cp.async.commit_group;\n" ::: "memory");                 \
    } while (0)

    LOAD_STAGE(0, 0);
    LOAD_STAGE(1, 1);
    LOAD_STAGE(2, 2);

    for (int kt = 0; kt < NKT; kt++) {
        int ahead = NKT - 1 - kt;
        if (ahead >= 2)      asm volatile("cp.async.wait_group 2;\n" ::: "memory");
        else if (ahead == 1) asm volatile("cp.async.wait_group 1;\n" ::: "memory");
        else                 asm volatile("cp.async.wait_group 0;\n" ::: "memory");
        __syncthreads();

        if (kt + 3 < NKT) LOAD_STAGE((kt + 3) & 3, kt + 3);

        const uint32_t sA = sbase + (kt & 3) * STAGE_B;

#pragma unroll
        for (int ks = 0; ks < 2; ks++) {       // two k16 steps (+32 bytes each)
            const uint32_t ko = ks * 32;
            unsigned af[4][4];
            unsigned bf[8][2];
#pragma unroll
            for (int mi = 0; mi < 4; mi++)
                ldsm4(af[mi][0], af[mi][1], af[mi][2], af[mi][3],
                      sA + aoff[mi] + ko);
#pragma unroll
            for (int p = 0; p < 4; p++)
                ldsm4(bf[2 * p][0], bf[2 * p][1], bf[2 * p + 1][0], bf[2 * p + 1][1],
                      sA + boff[p] + ko);
#pragma unroll
            for (int mi = 0; mi < 4; mi++)
#pragma unroll
                for (int ni = 0; ni < 8; ni++)
                    mma_f16(acc[mi][ni], af[mi], bf[ni]);
        }
    }

    // epilogue (fp32 out)
#pragma unroll
    for (int mi = 0; mi < 4; mi++) {
        int r0 = bm + wm + mi * 16 + gp;
#pragma unroll
        for (int ni = 0; ni < 8; ni++) {
            int c0 = bn + wn + ni * 8 + tg * 2;
            *(float2*)&D[(size_t)r0 * CC + c0]       = make_float2(acc[mi][ni][0], acc[mi][ni][1]);
            *(float2*)&D[(size_t)(r0 + 8) * CC + c0] = make_float2(acc[mi][ni][2], acc[mi][ni][3]);
        }
    }
#undef LOAD_STAGE
}

__global__ __launch_bounds__(128, 2) void gemm_fused3()
{
    extern __shared__ char smem[];
    const __half* A;
    const __half* B;
    float* D;
    if (blockIdx.z == 0)      { A = g_xk; B = g_WkT; D = g_k; }
    else if (blockIdx.z == 1) { A = g_xv; B = g_WvT; D = g_v; }
    else                      { A = g_xr; B = g_WrT; D = g_r; }
    gemm_body(A, B, D, smem);
}

__global__ __launch_bounds__(128, 2) void gemm_single(
    const __half* __restrict__ A, const __half* __restrict__ Bt, float* __restrict__ D)
{
    extern __shared__ char smem[];
    gemm_body(A, Bt, D, smem);
}

// ---------------------------------------------------------------------------
// WKV chunk-parallel scan; A/C process 4 channels/thread (float4 loads);
// chunk-state arrays are channel-major [c*NCHUNK+ch] for phaseB coalescing.
// ---------------------------------------------------------------------------
__global__ __launch_bounds__(128) void wkv_phaseA(const float* __restrict__ time_decay)
{
    int t = blockIdx.x * 128 + threadIdx.x;       // 0..511
    int c = t * 4;
    int ch = blockIdx.y;
    float4 td4 = *(const float4*)&time_decay[c];
    float w[4] = {-__expf(td4.x), -__expf(td4.y), -__expf(td4.z), -__expf(td4.w)};
    float p[4] = {0.f, 0.f, 0.f, 0.f};
    float q[4] = {0.f, 0.f, 0.f, 0.f};
    float o[4] = {-CUDART_INF_F, -CUDART_INF_F, -CUDART_INF_F, -CUDART_INF_F};
    size_t idx = (size_t)(ch * CHUNK) * CC + c;
#pragma unroll 2
    for (int i = 0; i < CHUNK; i++, idx += CC) {
        float4 kt4 = *(const float4*)&g_k[idx];
        float4 vt4 = *(const float4*)&g_v[idx];
        float kt[4] = {kt4.x, kt4.y, kt4.z, kt4.w};
        float vt[4] = {vt4.x, vt4.y, vt4.z, vt4.w};
#pragma unroll
        for (int j = 0; j < 4; j++) {
            float no = fmaxf(w[j] + o[j], kt[j]);
            float A2 = __expf(w[j] + o[j] - no);
            float B2 = __expf(kt[j] - no);
            p[j] = A2 * p[j] + B2 * vt[j];
            q[j] = A2 * q[j] + B2;
            o[j] = no;
        }
    }
#pragma unroll
    for (int j = 0; j < 4; j++) {
        g_lp[(c + j) * NCHUNK + ch] = p[j];
        g_lq[(c + j) * NCHUNK + ch] = q[j];
        g_lo[(c + j) * NCHUNK + ch] = o[j];
    }
}

// Warp-scan carry combine: one warp per channel, lane l holds chunks 4l..4l+3.
__global__ __launch_bounds__(256) void wkv_phaseB(const float* __restrict__ time_decay)
{
    const int lane = threadIdx.x & 31;
    const int c = blockIdx.x * 8 + (threadIdx.x >> 5);   // grid 256
    const float w = -__expf(time_decay[c]);
    const float d = w * (float)CHUNK;

    const int base = c * NCHUNK + lane * 4;
    const float4 lp4 = *(const float4*)&g_lp[base];
    const float4 lq4 = *(const float4*)&g_lq[base];
    const float4 lo4 = *(const float4*)&g_lo[base];
    const float lp[4] = {lp4.x, lp4.y, lp4.z, lp4.w};
    const float lq[4] = {lq4.x, lq4.y, lq4.z, lq4.w};
    const float lo[4] = {lo4.x, lo4.y, lo4.z, lo4.w};

    float ep[4], eq[4], eo[4];
    float p = 0.f, q = 0.f, o = -CUDART_INF_F;
#pragma unroll
    for (int m = 0; m < 4; m++) {
        ep[m] = p; eq[m] = q; eo[m] = o;
        float o1 = o + d;
        float no = fmaxf(o1, lo[m]);
        float A = __expf(o1 - no);
        float B = __expf(lo[m] - no);
        p = A * p + B * lp[m];
        q = A * q + B * lq[m];
        o = no;
    }

#pragma unroll
    for (int k = 1; k <= 16; k <<= 1) {
        float pp = __shfl_up_sync(0xffffffffu, p, k);
        float qq = __shfl_up_sync(0xffffffffu, q, k);
        float oo = __shfl_up_sync(0xffffffffu, o, k);
        if (lane >= k) {
            float o1 = oo + d * (float)(4 * k);
            float no = fmaxf(o1, o);
            float A = __expf(o1 - no);
            float B = __expf(o - no);
            p = A * pp + B * p;
            q = A * qq + B * q;
            o = no;
        }
    }

    float Pp = __shfl_up_sync(0xffffffffu, p, 1);
    float Pq = __shfl_up_sync(0xffffffffu, q, 1);
    float Po = __shfl_up_sync(0xffffffffu, o, 1);
    if (lane == 0) { Pp = 0.f; Pq = 0.f; Po = -CUDART_INF_F; }

    float cp[4], cq[4], co[4];
    cp[0] = Pp; cq[0] = Pq; co[0] = Po;
#pragma unroll
    for (int m = 1; m < 4; m++) {
        float o1 = Po + d * (float)m;
        float no = fmaxf(o1, eo[m]);
        float A = __expf(o1 - no);
        float B = __expf(eo[m] - no);
        cp[m] = A * Pp + B * ep[m];
        cq[m] = A * Pq + B * eq[m];
        co[m] = no;
    }
    *(float4*)&g_cp[base] = make_float4(cp[0], cp[1], cp[2], cp[3]);
    *(float4*)&g_cq[base] = make_float4(cq[0], cq[1], cq[2], cq[3]);
    *(float4*)&g_co[base] = make_float4(co[0], co[1], co[2], co[3]);
}

// fuses sigmoid(r) gate; fp16 output (Wo GEMM A operand); 4 channels/thread
__global__ __launch_bounds__(128) void wkv_phaseC(
    const float* __restrict__ time_decay, const float* __restrict__ time_first)
{
    int t = blockIdx.x * 128 + threadIdx.x;       // 0..511
    int c = t * 4;
    int ch = blockIdx.y;
    float4 td4 = *(const float4*)&time_decay[c];
    float4 tf4 = *(const float4*)&time_first[c];
    float w[4] = {-__expf(td4.x), -__expf(td4.y), -__expf(td4.z), -__expf(td4.w)};
    float u[4] = {tf4.x, tf4.y, tf4.z, tf4.w};
    float p[4], q[4], o[4];
#pragma unroll
    for (int j = 0; j < 4; j++) {
        p[j] = g_cp[(c + j) * NCHUNK + ch];
        q[j] = g_cq[(c + j) * NCHUNK + ch];
        o[j] = g_co[(c + j) * NCHUNK + ch];
    }
    size_t idx = (size_t)(ch * CHUNK) * CC + c;
#pragma unroll 2
    for (int i = 0; i < CHUNK; i++, idx += CC) {
        float4 kt4 = *(const float4*)&g_k[idx];
        float4 vt4 = *(const float4*)&g_v[idx];
        float4 rt4 = *(const float4*)&g_r[idx];
        float kt[4] = {kt4.x, kt4.y, kt4.z, kt4.w};
        float vt[4] = {vt4.x, vt4.y, vt4.z, vt4.w};
        float rt[4] = {rt4.x, rt4.y, rt4.z, rt4.w};
        float yv[4];
#pragma unroll
        for (int j = 0; j < 4; j++) {
            float uk = u[j] + kt[j];
            float no = fmaxf(o[j], uk);
            float Ae = __expf(o[j] - no);
            float Be = __expf(uk - no);
            float y = __fdividef(Ae * p[j] + Be * vt[j], Ae * q[j] + Be);
            float sr = __fdividef(1.f, 1.f + __expf(-rt[j]));
            yv[j] = sr * y;
            float no2 = fmaxf(w[j] + o[j], kt[j]);
            float A2 = __expf(w[j] + o[j] - no2);
            float B2 = __expf(kt[j] - no2);
            p[j] = A2 * p[j] + B2 * vt[j];
            q[j] = A2 * q[j] + B2;
            o[j] = no2;
        }
        __half2 y01 = __floats2half2_rn(yv[0], yv[1]);
        __half2 y23 = __floats2half2_rn(yv[2], yv[3]);
        *(uint2*)&g_y[idx] = make_uint2(h2u(y01), h2u(y23));
    }
}

// ---------------------------------------------------------------------------
// Launch
// ---------------------------------------------------------------------------
extern "C" void kernel_launch(void* const* d_in, const int* in_sizes, int n_in,
                              void* d_out, int out_size)
{
    (void)in_sizes; (void)n_in; (void)out_size;
    const float* x   = (const float*)d_in[0];
    const float* tfi = (const float*)d_in[1];
    const float* tmk = (const float*)d_in[2];
    const float* tmv = (const float*)d_in[3];
    const float* tmr = (const float*)d_in[4];
    const float* td  = (const float*)d_in[5];
    const float* Wk  = (const float*)d_in[6];
    const float* Wv  = (const float*)d_in[7];
    const float* Wr  = (const float*)d_in[8];
    const float* Wo  = (const float*)d_in[9];
    float* out = (float*)d_out;

    __half *p_y, *p_WoT;
    cudaGetSymbolAddress((void**)&p_y,  g_y);
    cudaGetSymbolAddress((void**)&p_WoT, g_WoT);

    cudaFuncSetAttribute(gemm_fused3, cudaFuncAttributeMaxDynamicSharedMemorySize, SMEM_BYTES);
    cudaFuncSetAttribute(gemm_single, cudaFuncAttributeMaxDynamicSharedMemorySize, SMEM_BYTES);

    prep_kernel<<<TRANS_BLOCKS + MIX_BLOCKS, 256>>>(x, tmk, tmv, tmr, Wk, Wv, Wr, Wo);

    dim3 g3(CC / BN, TT / BM, 3);   // (16, 32, 3) = 1536 CTAs
    gemm_fused3<<<g3, 128, SMEM_BYTES>>>();

    wkv_phaseA<<<dim3(CC / 512, NCHUNK), 128>>>(td);
    wkv_phaseB<<<CC / 8, 256>>>(td);
    wkv_phaseC<<<dim3(CC / 512, NCHUNK), 128>>>(td, tfi);

    dim3 g1(CC / BN, TT / BM);      // (16, 32) = 512 CTAs
    gemm_single<<<g1, 128, SMEM_BYTES>>>(p_y, p_WoT, out);
}

// round 15
// speedup vs baseline: 1.0355x; 1.0043x over previous
#include <cuda_runtime.h>
#include <cuda_fp16.h>
#include <cstdint>
#include <math_constants.h>

// ---------------------------------------------------------------------------
// RWKV TimeMix: T=4096, C=2048
//   fp16 mma.sync GEMMs (128x128 tile, warp 64x64, occ 2, pitch-20 smem,
//   cp.async 4-stage, ldmatrix fragment loads) + chunk-parallel WKV scan
//   (128 chunks, 2ch/thread float2, warp-scan carry) + fused prep.
//   r projection in fp16 via dedicated kernel (no shared-kernel template).
// ---------------------------------------------------------------------------

#define TT 4096
#define CC 2048
#define NCHUNK 128
#define CHUNK (TT / NCHUNK)   // 32

// Scratch (device globals: no allocation allowed anywhere)
__device__ __half g_xk[TT * CC];
__device__ __half g_xv[TT * CC];
__device__ __half g_xr[TT * CC];
__device__ __half g_y [TT * CC];          // gated output (Wo GEMM A operand)
__device__ __half g_r [TT * CC];          // r projection (fp16: sigmoid input)
__device__ float  g_k [TT * CC];
__device__ float  g_v [TT * CC];
// chunk states, channel-major: [c * NCHUNK + ch]
__device__ float  g_lp[CC * NCHUNK];
__device__ float  g_lq[CC * NCHUNK];
__device__ float  g_lo[CC * NCHUNK];
__device__ float  g_cp[CC * NCHUNK];
__device__ float  g_cq[CC * NCHUNK];
__device__ float  g_co[CC * NCHUNK];
// K-major (transposed) weights, fp16
__device__ __half g_WkT[CC * CC];
__device__ __half g_WvT[CC * CC];
__device__ __half g_WrT[CC * CC];
__device__ __half g_WoT[CC * CC];

// ---------------------------------------------------------------------------
// Helpers
// ---------------------------------------------------------------------------
__device__ __forceinline__ uint32_t smem_u32(const void* p) {
    uint32_t a;
    asm("{ .reg .u64 t; cvta.to.shared.u64 t, %1; cvt.u32.u64 %0, t; }"
        : "=r"(a) : "l"(p));
    return a;
}

__device__ __forceinline__ unsigned h2u(__half2 h) {
    return *reinterpret_cast<unsigned*>(&h);
}

__device__ __forceinline__ void epi_store2(float* D, size_t off, float a, float b) {
    *(float2*)&D[off] = make_float2(a, b);
}
__device__ __forceinline__ void epi_store2(__half* D, size_t off, float a, float b) {
    *(__half2*)&D[off] = __floats2half2_rn(a, b);
}

// ---------------------------------------------------------------------------
// Fused prep: blocks [0, 8192) transpose the 4 weights -> fp16 K-major
//             (32n x 64k tiles, half2 coalesced writes);
//             blocks [8192, 16384) do the time-mix -> fp16 operands.
// ---------------------------------------------------------------------------
#define TRANS_BLOCKS (4 * (CC / 32) * (CC / 64))   // 8192
#define MIX_BLOCKS   ((TT * CC / 4) / 256)         // 8192

__global__ __launch_bounds__(256) void prep_kernel(
    const float* __restrict__ x,
    const float* __restrict__ tmk,
    const float* __restrict__ tmv,
    const float* __restrict__ tmr,
    const float* __restrict__ W0, const float* __restrict__ W1,
    const float* __restrict__ W2, const float* __restrict__ W3)
{
    const int bid = blockIdx.x;
    const int tid = threadIdx.x;

    if (bid < TRANS_BLOCKS) {
        __shared__ float t[64][33];      // [k][n] staging
        int z = bid >> 11;               // 2048 blocks per matrix
        int r = bid & 2047;
        int bx = (r & 63) * 32;          // n-tile base (CC/32 = 64 tiles)
        int by = (r >> 6) * 64;          // k-tile base (CC/64 = 32 tiles)
        const float* W;
        __half* WT;
        switch (z) {
            case 0:  W = W0; WT = g_WkT; break;
            case 1:  W = W1; WT = g_WvT; break;
            case 2:  W = W2; WT = g_WrT; break;
            default: W = W3; WT = g_WoT; break;
        }
        int tx = tid & 31, ty = tid >> 5;          // 32 x 8
#pragma unroll
        for (int j = 0; j < 64; j += 8)
            t[ty + j][tx] = W[(size_t)(by + ty + j) * CC + bx + tx];
        __syncthreads();
        // write: row n = bx+nn, cols k = by + 2tx, 2tx+1 as half2 (128B/warp)
#pragma unroll
        for (int j = 0; j < 32; j += 8) {
            int nn = ty + j;
            __half2 v = __floats2half2_rn(t[2 * tx][nn], t[2 * tx + 1][nn]);
            *(__half2*)&WT[(size_t)(bx + nn) * CC + by + 2 * tx] = v;
        }
        return;
    }

    // ---- mix ----
    int i4 = (bid - TRANS_BLOCKS) * 256 + tid;    // float4 index over T*C/4
    int c4 = i4 & (CC / 4 - 1);

    float4 xc = ((const float4*)x)[i4];
    float4 xp;
    if (i4 >= CC / 4) xp = ((const float4*)x)[i4 - CC / 4];
    else              xp = make_float4(0.f, 0.f, 0.f, 0.f);

    float4 mk = ((const float4*)tmk)[c4];
    float4 mv = ((const float4*)tmv)[c4];
    float4 mr = ((const float4*)tmr)[c4];

    __half2 k01 = __floats2half2_rn(xp.x + mk.x * (xc.x - xp.x), xp.y + mk.y * (xc.y - xp.y));
    __half2 k23 = __floats2half2_rn(xp.z + mk.z * (xc.z - xp.z), xp.w + mk.w * (xc.w - xp.w));
    __half2 v01 = __floats2half2_rn(xp.x + mv.x * (xc.x - xp.x), xp.y + mv.y * (xc.y - xp.y));
    __half2 v23 = __floats2half2_rn(xp.z + mv.z * (xc.z - xp.z), xp.w + mv.w * (xc.w - xp.w));
    __half2 r01 = __floats2half2_rn(xp.x + mr.x * (xc.x - xp.x), xp.y + mr.y * (xc.y - xp.y));
    __half2 r23 = __floats2half2_rn(xp.z + mr.z * (xc.z - xp.z), xp.w + mr.w * (xc.w - xp.w));

    ((uint2*)g_xk)[i4] = make_uint2(h2u(k01), h2u(k23));
    ((uint2*)g_xv)[i4] = make_uint2(h2u(v01), h2u(v23));
    ((uint2*)g_xr)[i4] = make_uint2(h2u(r01), h2u(r23));
}

// ---------------------------------------------------------------------------
// FP16 GEMM: D[M,N] = A[M,K] @ Bt[N,K]^T  (both k-contiguous, half)
// Block 128x128, BK=32, 128 threads (4 warps, warp tile 64x64),
// 4-stage cp.async pipeline, pitch-20-word smem, ldmatrix fragment loads.
// Template instantiated only in SEPARATE kernels (no register cross-talk).
// ---------------------------------------------------------------------------
#define BM 128
#define BN 128
#define BK 32
#define PITCHW 20                    // 32-bit words per row (32 halves + 8 pad)
#define PITCHB (PITCHW * 4)          // 80 bytes per row
#define AST_W (BM * PITCHW)          // 2560 words per A tile
#define STAGE_B (2 * AST_W * 4)      // 20480 bytes (A + B)
#define NSTAGE 4
#define SMEM_BYTES (NSTAGE * STAGE_B)   // 81920
#define NKT (CC / BK)                // 64

__device__ __forceinline__ void mma_f16(float* d, const unsigned* a, const unsigned* b) {
    asm volatile(
        "mma.sync.aligned.m16n8k16.row.col.f32.f16.f16.f32 "
        "{%0,%1,%2,%3}, {%4,%5,%6,%7}, {%8,%9}, {%0,%1,%2,%3};\n"
        : "+f"(d[0]), "+f"(d[1]), "+f"(d[2]), "+f"(d[3])
        : "r"(a[0]), "r"(a[1]), "r"(a[2]), "r"(a[3]), "r"(b[0]), "r"(b[1]));
}

__device__ __forceinline__ void cp16(uint32_t saddr, const void* gaddr) {
    asm volatile("cp.async.cg.shared.global [%0], [%1], 16;\n"
                 :: "r"(saddr), "l"(gaddr));
}

__device__ __forceinline__ void ldsm4(unsigned& r0, unsigned& r1,
                                      unsigned& r2, unsigned& r3, uint32_t addr) {
    asm volatile(
        "ldmatrix.sync.aligned.m8n8.x4.shared.b16 {%0,%1,%2,%3}, [%4];"
        : "=r"(r0), "=r"(r1), "=r"(r2), "=r"(r3) : "r"(addr));
}

template <typename OT>
__device__ __forceinline__ void gemm_body(
    const __half* __restrict__ A, const __half* __restrict__ Bt,
    OT* __restrict__ D, char* smem)
{
    const uint32_t sbase = smem_u32(smem);
    const int tid = threadIdx.x;
    const int wid = tid >> 5;
    const int lane = tid & 31;
    const int gp = lane >> 2;        // 0..7
    const int tg = lane & 3;         // 0..3
    const int wm = (wid & 1) << 6;   // 0, 64
    const int wn = (wid >> 1) << 6;  // 0, 64

    const int bm = blockIdx.y * BM;
    const int bn = blockIdx.x * BN;

    const int lr = tid >> 2;         // 0..31
    const int lc = tid & 3;          // 0..3
    const __half* ga = A  + (size_t)(bm + lr) * CC + lc * 8;
    const __half* gb = Bt + (size_t)(bn + lr) * CC + lc * 8;
    const uint32_t swa = (uint32_t)(lr * PITCHB + lc * 16);

    uint32_t aoff[4];
#pragma unroll
    for (int mi = 0; mi < 4; mi++)
        aoff[mi] = (uint32_t)((wm + mi * 16 + (lane & 15)) * PITCHB + (lane >> 4) * 16);
    uint32_t boff[4];
#pragma unroll
    for (int p = 0; p < 4; p++)
        boff[p] = (uint32_t)(AST_W * 4 +
                  (wn + p * 16 + (lane & 7) + ((lane >> 4) << 3)) * PITCHB +
                  ((lane >> 3) & 1) * 16);

    float acc[4][8][4];
#pragma unroll
    for (int i = 0; i < 4; i++)
#pragma unroll
        for (int j = 0; j < 8; j++)
#pragma unroll
            for (int e = 0; e < 4; e++) acc[i][j][e] = 0.f;

#define LOAD_STAGE(ST, KT)                                                     \
    do {                                                                       \
        uint32_t _sa = sbase + (ST) * STAGE_B + swa;                           \
        uint32_t _sb = _sa + AST_W * 4;                                        \
        const __half* _ga = ga + (KT) * BK;                                    \
        const __half* _gb = gb + (KT) * BK;                                    \
        cp16(_sa,                  _ga);                                       \
        cp16(_sa + 32 * PITCHB,    _ga + (size_t)32 * CC);                     \
        cp16(_sa + 64 * PITCHB,    _ga + (size_t)64 * CC);                     \
        cp16(_sa + 96 * PITCHB,    _ga + (size_t)96 * CC);                     \
        cp16(_sb,                  _gb);                                       \
        cp16(_sb + 32 * PITCHB,    _gb + (size_t)32 * CC);                     \
        cp16(_sb + 64 * PITCHB,    _gb + (size_t)64 * CC);                     \
        cp16(_sb + 96 * PITCHB,    _gb + (size_t)96 * CC);                     \
        asm volatile("cp.async.commit_group;\n" ::: "memory");                 \
    } while (0)

    LOAD_STAGE(0, 0);
    LOAD_STAGE(1, 1);
    LOAD_STAGE(2, 2);

    for (int kt = 0; kt < NKT; kt++) {
        int ahead = NKT - 1 - kt;
        if (ahead >= 2)      asm volatile("cp.async.wait_group 2;\n" ::: "memory");
        else if (ahead == 1) asm volatile("cp.async.wait_group 1;\n" ::: "memory");
        else                 asm volatile("cp.async.wait_group 0;\n" ::: "memory");
        __syncthreads();

        if (kt + 3 < NKT) LOAD_STAGE((kt + 3) & 3, kt + 3);

        const uint32_t sA = sbase + (kt & 3) * STAGE_B;

#pragma unroll
        for (int ks = 0; ks < 2; ks++) {       // two k16 steps (+32 bytes each)
            const uint32_t ko = ks * 32;
            unsigned af[4][4];
            unsigned bf[8][2];
#pragma unroll
            for (int mi = 0; mi < 4; mi++)
                ldsm4(af[mi][0], af[mi][1], af[mi][2], af[mi][3],
                      sA + aoff[mi] + ko);
#pragma unroll
            for (int p = 0; p < 4; p++)
                ldsm4(bf[2 * p][0], bf[2 * p][1], bf[2 * p + 1][0], bf[2 * p + 1][1],
                      sA + boff[p] + ko);
#pragma unroll
            for (int mi = 0; mi < 4; mi++)
#pragma unroll
                for (int ni = 0; ni < 8; ni++)
                    mma_f16(acc[mi][ni], af[mi], bf[ni]);
        }
    }

    // epilogue
#pragma unroll
    for (int mi = 0; mi < 4; mi++) {
        int r0 = bm + wm + mi * 16 + gp;
#pragma unroll
        for (int ni = 0; ni < 8; ni++) {
            int c0 = bn + wn + ni * 8 + tg * 2;
            epi_store2(D, (size_t)r0 * CC + c0,       acc[mi][ni][0], acc[mi][ni][1]);
            epi_store2(D, (size_t)(r0 + 8) * CC + c0, acc[mi][ni][2], acc[mi][ni][3]);
        }
    }
#undef LOAD_STAGE
}

// k and v GEMMs (fp32 out) — one fp32 instantiation only in this kernel
__global__ __launch_bounds__(128, 2) void gemm_fused2()
{
    extern __shared__ char smem[];
    if (blockIdx.z == 0) gemm_body<float>(g_xk, g_WkT, g_k, smem);
    else                 gemm_body<float>(g_xv, g_WvT, g_v, smem);
}

// r GEMM (fp16 out) — dedicated kernel, single fp16 instantiation
__global__ __launch_bounds__(128, 2) void gemm_r()
{
    extern __shared__ char smem[];
    gemm_body<__half>(g_xr, g_WrT, g_r, smem);
}

__global__ __launch_bounds__(128, 2) void gemm_single(
    const __half* __restrict__ A, const __half* __restrict__ Bt, float* __restrict__ D)
{
    extern __shared__ char smem[];
    gemm_body<float>(A, Bt, D, smem);
}

// ---------------------------------------------------------------------------
// WKV chunk-parallel scan; A/C process 2 channels/thread (float2 loads);
// chunk-state arrays are channel-major [c*NCHUNK+ch] for phaseB coalescing.
// (Exact R12 structure.)
// ---------------------------------------------------------------------------
__global__ __launch_bounds__(128) void wkv_phaseA(const float* __restrict__ time_decay)
{
    int t = blockIdx.x * 128 + threadIdx.x;       // 0..1023
    int c = t * 2;
    int ch = blockIdx.y;
    float2 td2 = *(const float2*)&time_decay[c];
    float wx = -__expf(td2.x), wy = -__expf(td2.y);
    float px = 0.f, qx = 0.f, ox = -CUDART_INF_F;
    float py = 0.f, qy = 0.f, oy = -CUDART_INF_F;
    size_t idx = (size_t)(ch * CHUNK) * CC + c;
#pragma unroll 4
    for (int i = 0; i < CHUNK; i++, idx += CC) {
        float2 kt = *(const float2*)&g_k[idx];
        float2 vt = *(const float2*)&g_v[idx];
        float nox = fmaxf(wx + ox, kt.x);
        float A2x = __expf(wx + ox - nox);
        float B2x = __expf(kt.x - nox);
        px = A2x * px + B2x * vt.x; qx = A2x * qx + B2x; ox = nox;
        float noy = fmaxf(wy + oy, kt.y);
        float A2y = __expf(wy + oy - noy);
        float B2y = __expf(kt.y - noy);
        py = A2y * py + B2y * vt.y; qy = A2y * qy + B2y; oy = noy;
    }
    g_lp[c * NCHUNK + ch] = px;  g_lp[(c + 1) * NCHUNK + ch] = py;
    g_lq[c * NCHUNK + ch] = qx;  g_lq[(c + 1) * NCHUNK + ch] = qy;
    g_lo[c * NCHUNK + ch] = ox;  g_lo[(c + 1) * NCHUNK + ch] = oy;
}

// Warp-scan carry combine: one warp per channel, lane l holds chunks 4l..4l+3.
__global__ __launch_bounds__(256) void wkv_phaseB(const float* __restrict__ time_decay)
{
    const int lane = threadIdx.x & 31;
    const int c = blockIdx.x * 8 + (threadIdx.x >> 5);   // grid 256
    const float w = -__expf(time_decay[c]);
    const float d = w * (float)CHUNK;

    const int base = c * NCHUNK + lane * 4;
    const float4 lp4 = *(const float4*)&g_lp[base];
    const float4 lq4 = *(const float4*)&g_lq[base];
    const float4 lo4 = *(const float4*)&g_lo[base];
    const float lp[4] = {lp4.x, lp4.y, lp4.z, lp4.w};
    const float lq[4] = {lq4.x, lq4.y, lq4.z, lq4.w};
    const float lo[4] = {lo4.x, lo4.y, lo4.z, lo4.w};

    float ep[4], eq[4], eo[4];
    float p = 0.f, q = 0.f, o = -CUDART_INF_F;
#pragma unroll
    for (int m = 0; m < 4; m++) {
        ep[m] = p; eq[m] = q; eo[m] = o;
        float o1 = o + d;
        float no = fmaxf(o1, lo[m]);
        float A = __expf(o1 - no);
        float B = __expf(lo[m] - no);
        p = A * p + B * lp[m];
        q = A * q + B * lq[m];
        o = no;
    }

#pragma unroll
    for (int k = 1; k <= 16; k <<= 1) {
        float pp = __shfl_up_sync(0xffffffffu, p, k);
        float qq = __shfl_up_sync(0xffffffffu, q, k);
        float oo = __shfl_up_sync(0xffffffffu, o, k);
        if (lane >= k) {
            float o1 = oo + d * (float)(4 * k);
            float no = fmaxf(o1, o);
            float A = __expf(o1 - no);
            float B = __expf(o - no);
            p = A * pp + B * p;
            q = A * qq + B * q;
            o = no;
        }
    }

    float Pp = __shfl_up_sync(0xffffffffu, p, 1);
    float Pq = __shfl_up_sync(0xffffffffu, q, 1);
    float Po = __shfl_up_sync(0xffffffffu, o, 1);
    if (lane == 0) { Pp = 0.f; Pq = 0.f; Po = -CUDART_INF_F; }

    float cp[4], cq[4], co[4];
    cp[0] = Pp; cq[0] = Pq; co[0] = Po;
#pragma unroll
    for (int m = 1; m < 4; m++) {
        float o1 = Po + d * (float)m;
        float no = fmaxf(o1, eo[m]);
        float A = __expf(o1 - no);
        float B = __expf(eo[m] - no);
        cp[m] = A * Pp + B * ep[m];
        cq[m] = A * Pq + B * eq[m];
        co[m] = no;
    }
    *(float4*)&g_cp[base] = make_float4(cp[0], cp[1], cp[2], cp[3]);
    *(float4*)&g_cq[base] = make_float4(cq[0], cq[1], cq[2], cq[3]);
    *(float4*)&g_co[base] = make_float4(co[0], co[1], co[2], co[3]);
}

// fuses sigmoid(r) gate; fp16 output (Wo GEMM A operand); 2 channels/thread
__global__ __launch_bounds__(128) void wkv_phaseC(
    const float* __restrict__ time_decay, const float* __restrict__ time_first)
{
    int t = blockIdx.x * 128 + threadIdx.x;
    int c = t * 2;
    int ch = blockIdx.y;
    float2 td2 = *(const float2*)&time_decay[c];
    float2 tf2 = *(const float2*)&time_first[c];
    float wx = -__expf(td2.x), wy = -__expf(td2.y);
    float px = g_cp[c * NCHUNK + ch], py = g_cp[(c + 1) * NCHUNK + ch];
    float qx = g_cq[c * NCHUNK + ch], qy = g_cq[(c + 1) * NCHUNK + ch];
    float ox = g_co[c * NCHUNK + ch], oy = g_co[(c + 1) * NCHUNK + ch];
    size_t idx = (size_t)(ch * CHUNK) * CC + c;
#pragma unroll 4
    for (int i = 0; i < CHUNK; i++, idx += CC) {
        float2 kt = *(const float2*)&g_k[idx];
        float2 vt = *(const float2*)&g_v[idx];
        unsigned rraw = *(const unsigned*)&g_r[idx];
        float2 rf = __half22float2(*reinterpret_cast<__half2*>(&rraw));
        float ukx = tf2.x + kt.x;
        float nox = fmaxf(ox, ukx);
        float Aex = __expf(ox - nox);
        float Bex = __expf(ukx - nox);
        float yx = __fdividef(Aex * px + Bex * vt.x, Aex * qx + Bex);
        float srx = __fdividef(1.f, 1.f + __expf(-rf.x));
        float no2x = fmaxf(wx + ox, kt.x);
        float A2x = __expf(wx + ox - no2x);
        float B2x = __expf(kt.x - no2x);
        px = A2x * px + B2x * vt.x; qx = A2x * qx + B2x; ox = no2x;
        float uky = tf2.y + kt.y;
        float noy = fmaxf(oy, uky);
        float Aey = __expf(oy - noy);
        float Bey = __expf(uky - noy);
        float yy = __fdividef(Aey * py + Bey * vt.y, Aey * qy + Bey);
        float sry = __fdividef(1.f, 1.f + __expf(-rf.y));
        float no2y = fmaxf(wy + oy, kt.y);
        float A2y = __expf(wy + oy - no2y);
        float B2y = __expf(kt.y - no2y);
        py = A2y * py + B2y * vt.y; qy = A2y * qy + B2y; oy = no2y;

        *(__half2*)&g_y[idx] = __floats2half2_rn(srx * yx, sry * yy);
    }
}

// ---------------------------------------------------------------------------
// Launch
// ---------------------------------------------------------------------------
extern "C" void kernel_launch(void* const* d_in, const int* in_sizes, int n_in,
                              void* d_out, int out_size)
{
    (void)in_sizes; (void)n_in; (void)out_size;
    const float* x   = (const float*)d_in[0];
    const float* tfi = (const float*)d_in[1];
    const float* tmk = (const float*)d_in[2];
    const float* tmv = (const float*)d_in[3];
    const float* tmr = (const float*)d_in[4];
    const float* td  = (const float*)d_in[5];
    const float* Wk  = (const float*)d_in[6];
    const float* Wv  = (const float*)d_in[7];
    const float* Wr  = (const float*)d_in[8];
    const float* Wo  = (const float*)d_in[9];
    float* out = (float*)d_out;

    __half *p_y, *p_WoT;
    cudaGetSymbolAddress((void**)&p_y,  g_y);
    cudaGetSymbolAddress((void**)&p_WoT, g_WoT);

    cudaFuncSetAttribute(gemm_fused2, cudaFuncAttributeMaxDynamicSharedMemorySize, SMEM_BYTES);
    cudaFuncSetAttribute(gemm_r,      cudaFuncAttributeMaxDynamicSharedMemorySize, SMEM_BYTES);
    cudaFuncSetAttribute(gemm_single, cudaFuncAttributeMaxDynamicSharedMemorySize, SMEM_BYTES);

    prep_kernel<<<TRANS_BLOCKS + MIX_BLOCKS, 256>>>(x, tmk, tmv, tmr, Wk, Wv, Wr, Wo);

    dim3 g2(CC / BN, TT / BM, 2);   // (16, 32, 2) = 1024 CTAs
    gemm_fused2<<<g2, 128, SMEM_BYTES>>>();
    dim3 g1(CC / BN, TT / BM);      // (16, 32) = 512 CTAs
    gemm_r<<<g1, 128, SMEM_BYTES>>>();

    wkv_phaseA<<<dim3(CC / 256, NCHUNK), 128>>>(td);
    wkv_phaseB<<<CC / 8, 256>>>(td);
    wkv_phaseC<<<dim3(CC / 256, NCHUNK), 128>>>(td, tfi);

    gemm_single<<<g1, 128, SMEM_BYTES>>>(p_y, p_WoT, out);
}

// round 17
// speedup vs baseline: 1.0561x; 1.0199x over previous
#include <cuda_runtime.h>
#include <cuda_fp16.h>
#include <cstdint>
#include <math_constants.h>

// ---------------------------------------------------------------------------
// RWKV TimeMix: T=4096, C=2048
//   fp16 mma.sync GEMMs (128x128 tile, warp 64x64, occ 2, pitch-20 smem,
//   cp.async 4-stage, ldmatrix fragment loads — exact R12 config) +
//   chunk-parallel WKV scan (128 chunks, 1ch/thread 256-thread A/C,
//   warp-scan carry) + fused transpose/mix prep.
// ---------------------------------------------------------------------------

#define TT 4096
#define CC 2048
#define NCHUNK 128
#define CHUNK (TT / NCHUNK)   // 32

// Scratch (device globals: no allocation allowed anywhere)
__device__ __half g_xk[TT * CC];
__device__ __half g_xv[TT * CC];
__device__ __half g_xr[TT * CC];
__device__ __half g_y [TT * CC];          // gated output (Wo GEMM A operand)
__device__ float  g_k [TT * CC];
__device__ float  g_v [TT * CC];
__device__ float  g_r [TT * CC];
// chunk states, channel-major: [c * NCHUNK + ch]
__device__ float  g_lp[CC * NCHUNK];
__device__ float  g_lq[CC * NCHUNK];
__device__ float  g_lo[CC * NCHUNK];
__device__ float  g_cp[CC * NCHUNK];
__device__ float  g_cq[CC * NCHUNK];
__device__ float  g_co[CC * NCHUNK];
// K-major (transposed) weights, fp16
__device__ __half g_WkT[CC * CC];
__device__ __half g_WvT[CC * CC];
__device__ __half g_WrT[CC * CC];
__device__ __half g_WoT[CC * CC];

// ---------------------------------------------------------------------------
// Helpers
// ---------------------------------------------------------------------------
__device__ __forceinline__ uint32_t smem_u32(const void* p) {
    uint32_t a;
    asm("{ .reg .u64 t; cvta.to.shared.u64 t, %1; cvt.u32.u64 %0, t; }"
        : "=r"(a) : "l"(p));
    return a;
}

__device__ __forceinline__ unsigned h2u(__half2 h) {
    return *reinterpret_cast<unsigned*>(&h);
}

// ---------------------------------------------------------------------------
// Fused prep: blocks [0, 16384) transpose the 4 weights -> fp16 K-major;
//             blocks [16384, 24576) do the time-mix -> fp16 operands.
// ---------------------------------------------------------------------------
#define TRANS_BLOCKS (4 * (CC / 32) * (CC / 32))   // 16384
#define MIX_BLOCKS   ((TT * CC / 4) / 256)         // 8192

__global__ __launch_bounds__(256) void prep_kernel(
    const float* __restrict__ x,
    const float* __restrict__ tmk,
    const float* __restrict__ tmv,
    const float* __restrict__ tmr,
    const float* __restrict__ W0, const float* __restrict__ W1,
    const float* __restrict__ W2, const float* __restrict__ W3)
{
    const int bid = blockIdx.x;
    const int tid = threadIdx.x;

    if (bid < TRANS_BLOCKS) {
        __shared__ float t[32][33];
        int z = bid >> 12;               // 4096 blocks per matrix
        int r = bid & 4095;
        int bx = (r & 63) * 32;
        int by = (r >> 6) * 32;
        const float* W;
        __half* WT;
        switch (z) {
            case 0:  W = W0; WT = g_WkT; break;
            case 1:  W = W1; WT = g_WvT; break;
            case 2:  W = W2; WT = g_WrT; break;
            default: W = W3; WT = g_WoT; break;
        }
        int tx = tid & 31, ty = tid >> 5;          // 32 x 8
#pragma unroll
        for (int j = 0; j < 32; j += 8)
            t[ty + j][tx] = W[(size_t)(by + ty + j) * CC + bx + tx];
        __syncthreads();
#pragma unroll
        for (int j = 0; j < 32; j += 8)
            WT[(size_t)(bx + ty + j) * CC + by + tx] = __float2half(t[tx][ty + j]);
        return;
    }

    // ---- mix ----
    int i4 = (bid - TRANS_BLOCKS) * 256 + tid;    // float4 index over T*C/4
    int c4 = i4 & (CC / 4 - 1);

    float4 xc = ((const float4*)x)[i4];
    float4 xp;
    if (i4 >= CC / 4) xp = ((const float4*)x)[i4 - CC / 4];
    else              xp = make_float4(0.f, 0.f, 0.f, 0.f);

    float4 mk = ((const float4*)tmk)[c4];
    float4 mv = ((const float4*)tmv)[c4];
    float4 mr = ((const float4*)tmr)[c4];

    __half2 k01 = __floats2half2_rn(xp.x + mk.x * (xc.x - xp.x), xp.y + mk.y * (xc.y - xp.y));
    __half2 k23 = __floats2half2_rn(xp.z + mk.z * (xc.z - xp.z), xp.w + mk.w * (xc.w - xp.w));
    __half2 v01 = __floats2half2_rn(xp.x + mv.x * (xc.x - xp.x), xp.y + mv.y * (xc.y - xp.y));
    __half2 v23 = __floats2half2_rn(xp.z + mv.z * (xc.z - xp.z), xp.w + mv.w * (xc.w - xp.w));
    __half2 r01 = __floats2half2_rn(xp.x + mr.x * (xc.x - xp.x), xp.y + mr.y * (xc.y - xp.y));
    __half2 r23 = __floats2half2_rn(xp.z + mr.z * (xc.z - xp.z), xp.w + mr.w * (xc.w - xp.w));

    ((uint2*)g_xk)[i4] = make_uint2(h2u(k01), h2u(k23));
    ((uint2*)g_xv)[i4] = make_uint2(h2u(v01), h2u(v23));
    ((uint2*)g_xr)[i4] = make_uint2(h2u(r01), h2u(r23));
}

// ---------------------------------------------------------------------------
// FP16 GEMM: D[M,N] = A[M,K] @ Bt[N,K]^T  (both k-contiguous, half)
// Block 128x128, BK=32, 128 threads (4 warps, warp tile 64x64),
// 4-stage cp.async pipeline, pitch-20-word smem, ldmatrix fragment loads.
// (Exact R12 configuration.)
// ---------------------------------------------------------------------------
#define BM 128
#define BN 128
#define BK 32
#define PITCHW 20                    // 32-bit words per row (32 halves + 8 pad)
#define PITCHB (PITCHW * 4)          // 80 bytes per row
#define AST_W (BM * PITCHW)          // 2560 words per A tile
#define STAGE_B (2 * AST_W * 4)      // 20480 bytes (A + B)
#define NSTAGE 4
#define SMEM_BYTES (NSTAGE * STAGE_B)   // 81920
#define NKT (CC / BK)                // 64

__device__ __forceinline__ void mma_f16(float* d, const unsigned* a, const unsigned* b) {
    asm volatile(
        "mma.sync.aligned.m16n8k16.row.col.f32.f16.f16.f32 "
        "{%0,%1,%2,%3}, {%4,%5,%6,%7}, {%8,%9}, {%0,%1,%2,%3};\n"
        : "+f"(d[0]), "+f"(d[1]), "+f"(d[2]), "+f"(d[3])
        : "r"(a[0]), "r"(a[1]), "r"(a[2]), "r"(a[3]), "r"(b[0]), "r"(b[1]));
}

__device__ __forceinline__ void cp16(uint32_t saddr, const void* gaddr) {
    asm volatile("cp.async.cg.shared.global [%0], [%1], 16;\n"
                 :: "r"(saddr), "l"(gaddr));
}

__device__ __forceinline__ void ldsm4(unsigned& r0, unsigned& r1,
                                      unsigned& r2, unsigned& r3, uint32_t addr) {
    asm volatile(
        "ldmatrix.sync.aligned.m8n8.x4.shared.b16 {%0,%1,%2,%3}, [%4];"
        : "=r"(r0), "=r"(r1), "=r"(r2), "=r"(r3) : "r"(addr));
}

__device__ __forceinline__ void gemm_body(
    const __half* __restrict__ A, const __half* __restrict__ Bt,
    float* __restrict__ D, char* smem)
{
    const uint32_t sbase = smem_u32(smem);
    const int tid = threadIdx.x;
    const int wid = tid >> 5;
    const int lane = tid & 31;
    const int gp = lane >> 2;        // 0..7
    const int tg = lane & 3;         // 0..3
    const int wm = (wid & 1) << 6;   // 0, 64
    const int wn = (wid >> 1) << 6;  // 0, 64

    const int bm = blockIdx.y * BM;
    const int bn = blockIdx.x * BN;

    const int lr = tid >> 2;         // 0..31
    const int lc = tid & 3;          // 0..3
    const __half* ga = A  + (size_t)(bm + lr) * CC + lc * 8;
    const __half* gb = Bt + (size_t)(bn + lr) * CC + lc * 8;
    const uint32_t swa = (uint32_t)(lr * PITCHB + lc * 16);

    // ldmatrix per-lane byte offsets (within stage)
    uint32_t aoff[4];
#pragma unroll
    for (int mi = 0; mi < 4; mi++)
        aoff[mi] = (uint32_t)((wm + mi * 16 + (lane & 15)) * PITCHB + (lane >> 4) * 16);
    uint32_t boff[4];
#pragma unroll
    for (int p = 0; p < 4; p++)
        boff[p] = (uint32_t)(AST_W * 4 +
                  (wn + p * 16 + (lane & 7) + ((lane >> 4) << 3)) * PITCHB +
                  ((lane >> 3) & 1) * 16);

    float acc[4][8][4];
#pragma unroll
    for (int i = 0; i < 4; i++)
#pragma unroll
        for (int j = 0; j < 8; j++)
#pragma unroll
            for (int e = 0; e < 4; e++) acc[i][j][e] = 0.f;

#define LOAD_STAGE(ST, KT)                                                     \
    do {                                                                       \
        uint32_t _sa = sbase + (ST) * STAGE_B + swa;                           \
        uint32_t _sb = _sa + AST_W * 4;                                        \
        const __half* _ga = ga + (KT) * BK;                                    \
        const __half* _gb = gb + (KT) * BK;                                    \
        cp16(_sa,                  _ga);                                       \
        cp16(_sa + 32 * PITCHB,    _ga + (size_t)32 * CC);                     \
        cp16(_sa + 64 * PITCHB,    _ga + (size_t)64 * CC);                     \
        cp16(_sa + 96 * PITCHB,    _ga + (size_t)96 * CC);                     \
        cp16(_sb,                  _gb);                                       \
        cp16(_sb + 32 * PITCHB,    _gb + (size_t)32 * CC);                     \
        cp16(_sb + 64 * PITCHB,    _gb + (size_t)64 * CC);                     \
        cp16(_sb + 96 * PITCHB,    _gb + (size_t)96 * CC);                     \
        asm volatile("cp.async.commit_group;\n" ::: "memory");                 \
    } while (0)

    LOAD_STAGE(0, 0);
    LOAD_STAGE(1, 1);
    LOAD_STAGE(2, 2);

    for (int kt = 0; kt < NKT; kt++) {
        int ahead = NKT - 1 - kt;
        if (ahead >= 2)      asm volatile("cp.async.wait_group 2;\n" ::: "memory");
        else if (ahead == 1) asm volatile("cp.async.wait_group 1;\n" ::: "memory");
        else                 asm volatile("cp.async.wait_group 0;\n" ::: "memory");
        __syncthreads();

        if (kt + 3 < NKT) LOAD_STAGE((kt + 3) & 3, kt + 3);

        const uint32_t sA = sbase + (kt & 3) * STAGE_B;

#pragma unroll
        for (int ks = 0; ks < 2; ks++) {       // two k16 steps (+32 bytes each)
            const uint32_t ko = ks * 32;
            unsigned af[4][4];
            unsigned bf[8][2];
#pragma unroll
            for (int mi = 0; mi < 4; mi++)
                ldsm4(af[mi][0], af[mi][1], af[mi][2], af[mi][3],
                      sA + aoff[mi] + ko);
#pragma unroll
            for (int p = 0; p < 4; p++)
                ldsm4(bf[2 * p][0], bf[2 * p][1], bf[2 * p + 1][0], bf[2 * p + 1][1],
                      sA + boff[p] + ko);
#pragma unroll
            for (int mi = 0; mi < 4; mi++)
#pragma unroll
                for (int ni = 0; ni < 8; ni++)
                    mma_f16(acc[mi][ni], af[mi], bf[ni]);
        }
    }

    // epilogue (fp32 out)
#pragma unroll
    for (int mi = 0; mi < 4; mi++) {
        int r0 = bm + wm + mi * 16 + gp;
#pragma unroll
        for (int ni = 0; ni < 8; ni++) {
            int c0 = bn + wn + ni * 8 + tg * 2;
            *(float2*)&D[(size_t)r0 * CC + c0]       = make_float2(acc[mi][ni][0], acc[mi][ni][1]);
            *(float2*)&D[(size_t)(r0 + 8) * CC + c0] = make_float2(acc[mi][ni][2], acc[mi][ni][3]);
        }
    }
#undef LOAD_STAGE
}

__global__ __launch_bounds__(128, 2) void gemm_fused3()
{
    extern __shared__ char smem[];
    const __half* A;
    const __half* B;
    float* D;
    if (blockIdx.z == 0)      { A = g_xk; B = g_WkT; D = g_k; }
    else if (blockIdx.z == 1) { A = g_xv; B = g_WvT; D = g_v; }
    else                      { A = g_xr; B = g_WrT; D = g_r; }
    gemm_body(A, B, D, smem);
}

__global__ __launch_bounds__(128, 2) void gemm_single(
    const __half* __restrict__ A, const __half* __restrict__ Bt, float* __restrict__ D)
{
    extern __shared__ char smem[];
    gemm_body(A, Bt, D, smem);
}

// ---------------------------------------------------------------------------
// WKV chunk-parallel scan; A/C: 256 threads, 1 channel/thread (measured-best
// shape, R10); chunk-state arrays channel-major [c*NCHUNK+ch] for phaseB.
// ---------------------------------------------------------------------------
__global__ __launch_bounds__(256) void wkv_phaseA(const float* __restrict__ time_decay)
{
    int c = blockIdx.x * 256 + threadIdx.x;
    int ch = blockIdx.y;
    float w = -__expf(time_decay[c]);
    float p = 0.f, q = 0.f, o = -CUDART_INF_F;
    size_t idx = (size_t)(ch * CHUNK) * CC + c;
#pragma unroll 4
    for (int i = 0; i < CHUNK; i++, idx += CC) {
        float kt = g_k[idx];
        float vt = g_v[idx];
        float no = fmaxf(w + o, kt);
        float A2 = __expf(w + o - no);
        float B2 = __expf(kt - no);
        p = A2 * p + B2 * vt;
        q = A2 * q + B2;
        o = no;
    }
    g_lp[c * NCHUNK + ch] = p;
    g_lq[c * NCHUNK + ch] = q;
    g_lo[c * NCHUNK + ch] = o;
}

// Warp-scan carry combine: one warp per channel, lane l holds chunks 4l..4l+3.
__global__ __launch_bounds__(256) void wkv_phaseB(const float* __restrict__ time_decay)
{
    const int lane = threadIdx.x & 31;
    const int c = blockIdx.x * 8 + (threadIdx.x >> 5);   // grid 256
    const float w = -__expf(time_decay[c]);
    const float d = w * (float)CHUNK;

    const int base = c * NCHUNK + lane * 4;
    const float4 lp4 = *(const float4*)&g_lp[base];
    const float4 lq4 = *(const float4*)&g_lq[base];
    const float4 lo4 = *(const float4*)&g_lo[base];
    const float lp[4] = {lp4.x, lp4.y, lp4.z, lp4.w};
    const float lq[4] = {lq4.x, lq4.y, lq4.z, lq4.w};
    const float lo[4] = {lo4.x, lo4.y, lo4.z, lo4.w};

    float ep[4], eq[4], eo[4];
    float p = 0.f, q = 0.f, o = -CUDART_INF_F;
#pragma unroll
    for (int m = 0; m < 4; m++) {
        ep[m] = p; eq[m] = q; eo[m] = o;
        float o1 = o + d;
        float no = fmaxf(o1, lo[m]);
        float A = __expf(o1 - no);
        float B = __expf(lo[m] - no);
        p = A * p + B * lp[m];
        q = A * q + B * lq[m];
        o = no;
    }

#pragma unroll
    for (int k = 1; k <= 16; k <<= 1) {
        float pp = __shfl_up_sync(0xffffffffu, p, k);
        float qq = __shfl_up_sync(0xffffffffu, q, k);
        float oo = __shfl_up_sync(0xffffffffu, o, k);
        if (lane >= k) {
            float o1 = oo + d * (float)(4 * k);
            float no = fmaxf(o1, o);
            float A = __expf(o1 - no);
            float B = __expf(o - no);
            p = A * pp + B * p;
            q = A * qq + B * q;
            o = no;
        }
    }

    float Pp = __shfl_up_sync(0xffffffffu, p, 1);
    float Pq = __shfl_up_sync(0xffffffffu, q, 1);
    float Po = __shfl_up_sync(0xffffffffu, o, 1);
    if (lane == 0) { Pp = 0.f; Pq = 0.f; Po = -CUDART_INF_F; }

    float cp[4], cq[4], co[4];
    cp[0] = Pp; cq[0] = Pq; co[0] = Po;
#pragma unroll
    for (int m = 1; m < 4; m++) {
        float o1 = Po + d * (float)m;
        float no = fmaxf(o1, eo[m]);
        float A = __expf(o1 - no);
        float B = __expf(eo[m] - no);
        cp[m] = A * Pp + B * ep[m];
        cq[m] = A * Pq + B * eq[m];
        co[m] = no;
    }
    *(float4*)&g_cp[base] = make_float4(cp[0], cp[1], cp[2], cp[3]);
    *(float4*)&g_cq[base] = make_float4(cq[0], cq[1], cq[2], cq[3]);
    *(float4*)&g_co[base] = make_float4(co[0], co[1], co[2], co[3]);
}

// fuses sigmoid(r) gate; fp16 output (Wo GEMM A operand); 1 channel/thread
__global__ __launch_bounds__(256) void wkv_phaseC(
    const float* __restrict__ time_decay, const float* __restrict__ time_first)
{
    int c = blockIdx.x * 256 + threadIdx.x;
    int ch = blockIdx.y;
    float w = -__expf(time_decay[c]);
    float u = time_first[c];
    float p = g_cp[c * NCHUNK + ch];
    float q = g_cq[c * NCHUNK + ch];
    float o = g_co[c * NCHUNK + ch];
    size_t idx = (size_t)(ch * CHUNK) * CC + c;
#pragma unroll 4
    for (int i = 0; i < CHUNK; i++, idx += CC) {
        float kt = g_k[idx];
        float vt = g_v[idx];
        float rt = g_r[idx];
        float uk = u + kt;
        float no = fmaxf(o, uk);
        float Ae = __expf(o - no);
        float Be = __expf(uk - no);
        float y = __fdividef(Ae * p + Be * vt, Ae * q + Be);
        float sr = __fdividef(1.f, 1.f + __expf(-rt));
        g_y[idx] = __float2half(sr * y);
        float no2 = fmaxf(w + o, kt);
        float A2 = __expf(w + o - no2);
        float B2 = __expf(kt - no2);
        p = A2 * p + B2 * vt;
        q = A2 * q + B2;
        o = no2;
    }
}

// ---------------------------------------------------------------------------
// Launch
// ---------------------------------------------------------------------------
extern "C" void kernel_launch(void* const* d_in, const int* in_sizes, int n_in,
                              void* d_out, int out_size)
{
    (void)in_sizes; (void)n_in; (void)out_size;
    const float* x   = (const float*)d_in[0];
    const float* tfi = (const float*)d_in[1];
    const float* tmk = (const float*)d_in[2];
    const float* tmv = (const float*)d_in[3];
    const float* tmr = (const float*)d_in[4];
    const float* td  = (const float*)d_in[5];
    const float* Wk  = (const float*)d_in[6];
    const float* Wv  = (const float*)d_in[7];
    const float* Wr  = (const float*)d_in[8];
    const float* Wo  = (const float*)d_in[9];
    float* out = (float*)d_out;

    __half *p_y, *p_WoT;
    cudaGetSymbolAddress((void**)&p_y,  g_y);
    cudaGetSymbolAddress((void**)&p_WoT, g_WoT);

    cudaFuncSetAttribute(gemm_fused3, cudaFuncAttributeMaxDynamicSharedMemorySize, SMEM_BYTES);
    cudaFuncSetAttribute(gemm_single, cudaFuncAttributeMaxDynamicSharedMemorySize, SMEM_BYTES);

    prep_kernel<<<TRANS_BLOCKS + MIX_BLOCKS, 256>>>(x, tmk, tmv, tmr, Wk, Wv, Wr, Wo);

    dim3 g3(CC / BN, TT / BM, 3);   // (16, 32, 3) = 1536 CTAs
    gemm_fused3<<<g3, 128, SMEM_BYTES>>>();

    wkv_phaseA<<<dim3(CC / 256, NCHUNK), 256>>>(td);
    wkv_phaseB<<<CC / 8, 256>>>(td);
    wkv_phaseC<<<dim3(CC / 256, NCHUNK), 256>>>(td, tfi);

    dim3 g1(CC / BN, TT / BM);      // (16, 32) = 512 CTAs
    gemm_single<<<g1, 128, SMEM_BYTES>>>(p_y, p_WoT, out);
}